// round 10
// baseline (speedup 1.0000x reference)
#include <cuda_runtime.h>
#include <cuda_bf16.h>
#include <cstdint>

#define NB 8
#define NH 16
#define SEQ 1024
#define DDIM 64
#define BM 128
#define BN 64
#define NTH 512
#define LOG2E 1.4426950408889634f

// SMEM: Q hi/lo (32KB) + 2 double-buffered K/V bf16 tile sets (32KB each)
#define SQH 0
#define SQL 16384
#define SBUF 32768
#define KVSTRIDE 32768
// within a KV buffer: KH +0, KL +8192, VH +16384, VL +24576
#define SMTOT (SBUF + 2 * KVSTRIDE)   // 98304

#define KVELEMS (NB * NH * SEQ * DDIM)   // 8,388,608

// pre-converted K/V in bf16 hi/lo, [b,h,n,d] row-major
__device__ __nv_bfloat16 g_khi[KVELEMS];
__device__ __nv_bfloat16 g_klo[KVELEMS];
__device__ __nv_bfloat16 g_vhi[KVELEMS];
__device__ __nv_bfloat16 g_vlo[KVELEMS];

__device__ __forceinline__ uint32_t smem_u32(const void* p) {
    uint32_t a;
    asm("{ .reg .u64 t; cvta.to.shared.u64 t, %1; cvt.u32.u64 %0, t; }" : "=r"(a) : "l"(p));
    return a;
}
__device__ __forceinline__ uint32_t sw(uint32_t o) { return o ^ ((o >> 3) & 0x70); }

__device__ __forceinline__ void ldsm4(uint32_t& r0, uint32_t& r1, uint32_t& r2, uint32_t& r3,
                                      uint32_t a) {
    asm volatile("ldmatrix.sync.aligned.m8n8.x4.shared.b16 {%0,%1,%2,%3},[%4];"
                 : "=r"(r0), "=r"(r1), "=r"(r2), "=r"(r3) : "r"(a));
}
__device__ __forceinline__ void ldsm4t(uint32_t& r0, uint32_t& r1, uint32_t& r2, uint32_t& r3,
                                       uint32_t a) {
    asm volatile("ldmatrix.sync.aligned.m8n8.x4.trans.shared.b16 {%0,%1,%2,%3},[%4];"
                 : "=r"(r0), "=r"(r1), "=r"(r2), "=r"(r3) : "r"(a));
}
__device__ __forceinline__ void mma16816(float* c, uint32_t a0, uint32_t a1, uint32_t a2,
                                         uint32_t a3, uint32_t b0, uint32_t b1) {
    asm volatile("mma.sync.aligned.m16n8k16.row.col.f32.bf16.bf16.f32 "
                 "{%0,%1,%2,%3},{%4,%5,%6,%7},{%8,%9},{%0,%1,%2,%3};"
                 : "+f"(c[0]), "+f"(c[1]), "+f"(c[2]), "+f"(c[3])
                 : "r"(a0), "r"(a1), "r"(a2), "r"(a3), "r"(b0), "r"(b1));
}
// pack (x0,x1) -> bf16x2 hi part + bf16x2 residual part
__device__ __forceinline__ void split2(float x0, float x1, uint32_t& hi, uint32_t& lo) {
    uint32_t hh;
    asm("cvt.rn.bf16x2.f32 %0, %1, %2;" : "=r"(hh) : "f"(x1), "f"(x0));
    float h0 = __uint_as_float(hh << 16);
    float h1 = __uint_as_float(hh & 0xffff0000u);
    float l0 = x0 - h0, l1 = x1 - h1;
    uint32_t ll;
    asm("cvt.rn.bf16x2.f32 %0, %1, %2;" : "=r"(ll) : "f"(l1), "f"(l0));
    hi = hh; lo = ll;
}
__device__ __forceinline__ void cpasync16(uint32_t dst, const void* src) {
    asm volatile("cp.async.cg.shared.global [%0], [%1], 16;" :: "r"(dst), "l"(src));
}

// ---- prepass: convert K,V fp32 -> bf16 hi/lo, once for the whole problem ----
__global__ __launch_bounds__(256)
void conv_kv(const float4* __restrict__ k4, const float4* __restrict__ v4)
{
    const int i = blockIdx.x * 256 + threadIdx.x;   // one float4 (4 elems) each
    float4 a = k4[i];
    uint2 hi, lo;
    split2(a.x, a.y, hi.x, lo.x);
    split2(a.z, a.w, hi.y, lo.y);
    ((uint2*)g_khi)[i] = hi;
    ((uint2*)g_klo)[i] = lo;
    float4 b = v4[i];
    split2(b.x, b.y, hi.x, lo.x);
    split2(b.z, b.w, hi.y, lo.y);
    ((uint2*)g_vhi)[i] = hi;
    ((uint2*)g_vlo)[i] = lo;
}

__global__ __launch_bounds__(NTH, 1)
void attn_mma(const float* __restrict__ q, const int* __restrict__ mask,
              const float* __restrict__ bias, float* __restrict__ out)
{
    extern __shared__ char smem[];
    __shared__ int s_len;
    __shared__ float s_li[2][128];
    const int tid  = threadIdx.x;
    const int lane = tid & 31;
    const int w    = tid >> 5;
    const int w_m  = w & 7;        // row group: rows 16*w_m .. +15
    const int w_n  = w >> 3;       // key half: keys 32*w_n .. +31 of each tile
    const int nh   = 32 * w_n;
    const int rowg = 16 * w_m;
    const int m0   = blockIdx.x * BM;
    const int h    = blockIdx.y;
    const int b    = blockIdx.z;
    const int bh   = b * NH + h;
    const uint32_t sb = smem_u32(smem);

    // per-thread cp.async slice: this half loads ONLY its own 32 rows
    const int g    = tid & 255;                // id within the 256-thread half
    const int kr   = nh + (g >> 3);            // tile row (nh..nh+31)
    const int cc   = (g & 7) * 8;              // elem col base (8 bf16 = 16B chunk)
    const uint32_t kvoff = sw((uint32_t)kr * 128 + (uint32_t)cc * 2);
    const size_t   gsrc0 = ((size_t)bh * SEQ + kr) * DDIM + cc;

    // ---- issue tile-0 K/V cp.async immediately (overlaps Q conversion) ----
    {
        const uint32_t d = sb + SBUF + kvoff;
        cpasync16(d + 0,     g_khi + gsrc0);
        cpasync16(d + 8192,  g_klo + gsrc0);
        cpasync16(d + 16384, g_vhi + gsrc0);
        cpasync16(d + 24576, g_vlo + gsrc0);
        asm volatile("cp.async.commit_group;" ::: "memory");
    }

    if (tid == 0) s_len = 0;
    __syncthreads();
    {   // valid length (mask int32 0/1, monotone prefix)
        const int* mb = mask + (size_t)b * SEQ;
        int part = 0;
        for (int i = tid; i < SEQ; i += NTH) part += (mb[i] != 0);
        #pragma unroll
        for (int o = 16; o > 0; o >>= 1) part += __shfl_xor_sync(0xffffffffu, part, o);
        if (lane == 0) atomicAdd(&s_len, part);
    }

    // ---- Q tile fp32 -> bf16 hi/lo, swizzled [row][d] 128B rows ----
    {
        const int row  = tid >> 2;                 // 0..127
        const int colf = (tid & 3) * 16;           // float col base
        const float* qrow = q + (((size_t)bh) * SEQ + m0 + row) * DDIM + colf;
        #pragma unroll
        for (int c = 0; c < 2; c++) {              // 2 chunks of 8 floats
            float4 t0 = *(const float4*)(qrow + 8 * c);
            float4 t1 = *(const float4*)(qrow + 8 * c + 4);
            uint4 hv, lv;
            split2(t0.x, t0.y, hv.x, lv.x);
            split2(t0.z, t0.w, hv.y, lv.y);
            split2(t1.x, t1.y, hv.z, lv.z);
            split2(t1.z, t1.w, hv.w, lv.w);
            uint32_t off = sw(row * 128 + colf * 2 + 16 * c);
            *(uint4*)(smem + SQH + off) = hv;
            *(uint4*)(smem + SQL + off) = lv;
        }
    }
    __syncthreads();
    const int len = s_len;
    const int n_tiles = (len + BN - 1) / BN;

    // ldmatrix per-lane addressing pattern
    const int r8  = (lane & 7) + ((lane >> 3) & 1) * 8;
    const int c16 = ((lane >> 4) & 1) * 16;

    float o[8][4];
    #pragma unroll
    for (int i = 0; i < 8; i++)
        #pragma unroll
        for (int j = 0; j < 4; j++) o[i][j] = 0.0f;
    float li1 = 0.0f, li2 = 0.0f;

    const float* bp1 = bias + ((size_t)h * SEQ + (m0 + rowg + (lane >> 2))) * SEQ;
    const float* bp2 = bp1 + 8 * SEQ;

    for (int t = 0; t < n_tiles; t++) {
        const int n0 = t * BN;
        const uint32_t kvb = sb + SBUF + (uint32_t)(t & 1) * KVSTRIDE;

        // ---- bias prefetch (pre-scaled by log2(e); overlaps the wait) ----
        float2 bb1[4], bb2[4];
        #pragma unroll
        for (int nb = 0; nb < 4; nb++) {
            int c = n0 + nh + 8 * nb + (lane & 3) * 2;
            bb1[nb] = *(const float2*)(bp1 + c);
            bb2[nb] = *(const float2*)(bp2 + c);
            bb1[nb].x *= LOG2E; bb1[nb].y *= LOG2E;
            bb2[nb].x *= LOG2E; bb2[nb].y *= LOG2E;
        }

        // ---- tile t's cp.async group (issued last iteration) must be done ----
        asm volatile("cp.async.wait_group 0;" ::: "memory");
        asm volatile("bar.sync %0, 256;" :: "r"(1 + w_n) : "memory");

        // ---- issue next tile's K/V into the other buffer (WAR-safe: all
        //      reads of that buffer happened before the barrier above) ----
        if (t + 1 < n_tiles) {
            const uint32_t d = sb + SBUF + (uint32_t)((t + 1) & 1) * KVSTRIDE + kvoff;
            const size_t src = gsrc0 + (size_t)(t + 1) * BN * DDIM;
            cpasync16(d + 0,     g_khi + src);
            cpasync16(d + 8192,  g_klo + src);
            cpasync16(d + 16384, g_vhi + src);
            cpasync16(d + 24576, g_vlo + src);
        }
        asm volatile("cp.async.commit_group;" ::: "memory");

        // ---- GEMM1: S = QK^T over this warp's 32-key half, 3-way split ----
        float s[4][4];
        #pragma unroll
        for (int i = 0; i < 4; i++)
            #pragma unroll
            for (int j = 0; j < 4; j++) s[i][j] = 0.0f;
        #pragma unroll
        for (int kbk = 0; kbk < 4; kbk++) {
            uint32_t qoff = sw((rowg + r8) * 128 + 32 * kbk + c16);
            uint32_t a0, a1, a2, a3, e0, e1, e2, e3;
            ldsm4(a0, a1, a2, a3, sb + SQH + qoff);
            ldsm4(e0, e1, e2, e3, sb + SQL + qoff);
            #pragma unroll
            for (int nbp = 0; nbp < 2; nbp++) {
                uint32_t boff = sw((nh + 16 * nbp + r8) * 128 + 32 * kbk + c16);
                uint32_t bh0, bh1, bh2, bh3, bl0, bl1, bl2, bl3;
                ldsm4(bh0, bh1, bh2, bh3, kvb + boff);
                ldsm4(bl0, bl1, bl2, bl3, kvb + 8192 + boff);
                mma16816(s[2 * nbp],     a0, a1, a2, a3, bh0, bh2);
                mma16816(s[2 * nbp + 1], a0, a1, a2, a3, bh1, bh3);
                mma16816(s[2 * nbp],     e0, e1, e2, e3, bh0, bh2);
                mma16816(s[2 * nbp + 1], e0, e1, e2, e3, bh1, bh3);
                mma16816(s[2 * nbp],     a0, a1, a2, a3, bl0, bl2);
                mma16816(s[2 * nbp + 1], a0, a1, a2, a3, bl1, bl3);
            }
        }

        // ---- softmax: p = exp2(s*log2e + bias*log2e), no max-sub ----
        uint32_t pah[2][4], pal[2][4];
        #pragma unroll
        for (int nb = 0; nb < 4; nb++) {
            int n = n0 + nh + 8 * nb + (lane & 3) * 2;
            float p0 = (n     < len) ? exp2f(fmaf(s[nb][0], LOG2E, bb1[nb].x)) : 0.0f;
            float p1 = (n + 1 < len) ? exp2f(fmaf(s[nb][1], LOG2E, bb1[nb].y)) : 0.0f;
            float p2 = (n     < len) ? exp2f(fmaf(s[nb][2], LOG2E, bb2[nb].x)) : 0.0f;
            float p3 = (n + 1 < len) ? exp2f(fmaf(s[nb][3], LOG2E, bb2[nb].y)) : 0.0f;
            li1 += p0 + p1;
            li2 += p2 + p3;
            split2(p0, p1, pah[nb >> 1][(nb & 1) * 2],     pal[nb >> 1][(nb & 1) * 2]);
            split2(p2, p3, pah[nb >> 1][(nb & 1) * 2 + 1], pal[nb >> 1][(nb & 1) * 2 + 1]);
        }

        // ---- GEMM2: O(partial) += P V over this warp's 32 keys ----
        const uint32_t vh_ = kvb + 16384;
        const uint32_t vl_ = kvb + 24576;
        #pragma unroll
        for (int kk = 0; kk < 2; kk++) {
            #pragma unroll
            for (int nbp = 0; nbp < 4; nbp++) {
                uint32_t voff = sw((nh + 16 * kk + r8) * 128 + 32 * nbp + c16);
                uint32_t vh0, vh1, vh2, vh3, vl0, vl1, vl2, vl3;
                ldsm4t(vh0, vh1, vh2, vh3, vh_ + voff);
                ldsm4t(vl0, vl1, vl2, vl3, vl_ + voff);
                mma16816(o[2 * nbp],     pah[kk][0], pah[kk][1], pah[kk][2], pah[kk][3], vh0, vh1);
                mma16816(o[2 * nbp + 1], pah[kk][0], pah[kk][1], pah[kk][2], pah[kk][3], vh2, vh3);
                mma16816(o[2 * nbp],     pal[kk][0], pal[kk][1], pal[kk][2], pal[kk][3], vh0, vh1);
                mma16816(o[2 * nbp + 1], pal[kk][0], pal[kk][1], pal[kk][2], pal[kk][3], vh2, vh3);
                mma16816(o[2 * nbp],     pah[kk][0], pah[kk][1], pah[kk][2], pah[kk][3], vl0, vl1);
                mma16816(o[2 * nbp + 1], pah[kk][0], pah[kk][1], pah[kk][2], pah[kk][3], vl2, vl3);
            }
        }
    }

    // ---- reduce li across the quad (lanes l^1, l^2 hold the same rows) ----
    li1 += __shfl_xor_sync(0xffffffffu, li1, 1);
    li1 += __shfl_xor_sync(0xffffffffu, li1, 2);
    li2 += __shfl_xor_sync(0xffffffffu, li2, 1);
    li2 += __shfl_xor_sync(0xffffffffu, li2, 2);

    // ---- combine the two key-halves: O(partial) and li through smem ----
    __syncthreads();   // all GEMM2 smem reads done; safe to alias KV buffer 0
    float* oshare = (float*)(smem + SBUF);   // [128][64] fp32 = 32KB
    const int r1 = rowg + (lane >> 2);
    if (w_n == 1) {
        #pragma unroll
        for (int nb = 0; nb < 8; nb++) {
            int c = 8 * nb + (lane & 3) * 2;
            *(float2*)(oshare + r1 * 64 + c)       = make_float2(o[nb][0], o[nb][1]);
            *(float2*)(oshare + (r1 + 8) * 64 + c) = make_float2(o[nb][2], o[nb][3]);
        }
        if ((lane & 3) == 0) {
            s_li[1][r1]     = li1;
            s_li[1][r1 + 8] = li2;
        }
    }
    __syncthreads();

    if (w_n == 0) {
        const float lt1 = li1 + s_li[1][r1];
        const float lt2 = li2 + s_li[1][r1 + 8];
        const float inv1 = ((m0 + r1)     < len) ? (1.0f / lt1) : 0.0f;
        const float inv2 = ((m0 + r1 + 8) < len) ? (1.0f / lt2) : 0.0f;
        float* o1 = out + ((size_t)b * SEQ + m0 + r1) * (NH * DDIM) + (size_t)h * DDIM;
        float* o2 = o1 + 8 * (NH * DDIM);
        #pragma unroll
        for (int nb = 0; nb < 8; nb++) {
            int c = 8 * nb + (lane & 3) * 2;
            float2 q1 = *(const float2*)(oshare + r1 * 64 + c);
            float2 q2 = *(const float2*)(oshare + (r1 + 8) * 64 + c);
            float2 w1 = {(o[nb][0] + q1.x) * inv1, (o[nb][1] + q1.y) * inv1};
            float2 w2 = {(o[nb][2] + q2.x) * inv2, (o[nb][3] + q2.y) * inv2};
            *(float2*)(o1 + c) = w1;
            *(float2*)(o2 + c) = w2;
        }
    }
}

extern "C" void kernel_launch(void* const* d_in, const int* in_sizes, int n_in,
                              void* d_out, int out_size)
{
    const float* q    = (const float*)d_in[0];
    const float* k    = (const float*)d_in[1];
    const float* v    = (const float*)d_in[2];
    const int*   mask = (const int*)d_in[3];
    const float* bias = (const float*)d_in[4];
    float* out = (float*)d_out;

    conv_kv<<<KVELEMS / 4 / 256, 256>>>((const float4*)k, (const float4*)v);

    cudaFuncSetAttribute(attn_mma, cudaFuncAttributeMaxDynamicSharedMemorySize, SMTOT);
    dim3 grid(SEQ / BM, NH, NB);
    attn_mma<<<grid, NTH, SMTOT>>>(q, mask, bias, out);
}

// round 11
// speedup vs baseline: 1.0351x; 1.0351x over previous
#include <cuda_runtime.h>
#include <cuda_bf16.h>
#include <cstdint>

#define NB 8
#define NH 16
#define SEQ 1024
#define DDIM 64
#define BM 64
#define BN 64
#define NTH 256
#define LOG2E 1.4426950408889634f

// SMEM: Q hi/lo (16KB) + 2 double-buffered K/V bf16 tile sets (32KB each)
#define SQH 0
#define SQL 8192
#define SBUF 16384
#define KVSTRIDE 32768
// within a KV buffer: KH +0, KL +8192, VH +16384, VL +24576
#define SMTOT (SBUF + 2 * KVSTRIDE)   // 81920

#define KVELEMS (NB * NH * SEQ * DDIM)   // 8,388,608

// pre-converted K/V in bf16 hi/lo, [b,h,n,d] row-major
__device__ __nv_bfloat16 g_khi[KVELEMS];
__device__ __nv_bfloat16 g_klo[KVELEMS];
__device__ __nv_bfloat16 g_vhi[KVELEMS];
__device__ __nv_bfloat16 g_vlo[KVELEMS];

__device__ __forceinline__ uint32_t smem_u32(const void* p) {
    uint32_t a;
    asm("{ .reg .u64 t; cvta.to.shared.u64 t, %1; cvt.u32.u64 %0, t; }" : "=r"(a) : "l"(p));
    return a;
}
__device__ __forceinline__ uint32_t sw(uint32_t o) { return o ^ ((o >> 3) & 0x70); }

__device__ __forceinline__ void ldsm4(uint32_t& r0, uint32_t& r1, uint32_t& r2, uint32_t& r3,
                                      uint32_t a) {
    asm volatile("ldmatrix.sync.aligned.m8n8.x4.shared.b16 {%0,%1,%2,%3},[%4];"
                 : "=r"(r0), "=r"(r1), "=r"(r2), "=r"(r3) : "r"(a));
}
__device__ __forceinline__ void ldsm4t(uint32_t& r0, uint32_t& r1, uint32_t& r2, uint32_t& r3,
                                       uint32_t a) {
    asm volatile("ldmatrix.sync.aligned.m8n8.x4.trans.shared.b16 {%0,%1,%2,%3},[%4];"
                 : "=r"(r0), "=r"(r1), "=r"(r2), "=r"(r3) : "r"(a));
}
__device__ __forceinline__ void mma16816(float* c, uint32_t a0, uint32_t a1, uint32_t a2,
                                         uint32_t a3, uint32_t b0, uint32_t b1) {
    asm volatile("mma.sync.aligned.m16n8k16.row.col.f32.bf16.bf16.f32 "
                 "{%0,%1,%2,%3},{%4,%5,%6,%7},{%8,%9},{%0,%1,%2,%3};"
                 : "+f"(c[0]), "+f"(c[1]), "+f"(c[2]), "+f"(c[3])
                 : "r"(a0), "r"(a1), "r"(a2), "r"(a3), "r"(b0), "r"(b1));
}
// pack (x0,x1) -> bf16x2 hi part + bf16x2 residual part
__device__ __forceinline__ void split2(float x0, float x1, uint32_t& hi, uint32_t& lo) {
    uint32_t hh;
    asm("cvt.rn.bf16x2.f32 %0, %1, %2;" : "=r"(hh) : "f"(x1), "f"(x0));
    float h0 = __uint_as_float(hh << 16);
    float h1 = __uint_as_float(hh & 0xffff0000u);
    float l0 = x0 - h0, l1 = x1 - h1;
    uint32_t ll;
    asm("cvt.rn.bf16x2.f32 %0, %1, %2;" : "=r"(ll) : "f"(l1), "f"(l0));
    hi = hh; lo = ll;
}
__device__ __forceinline__ void cpasync16(uint32_t dst, const void* src) {
    asm volatile("cp.async.cg.shared.global [%0], [%1], 16;" :: "r"(dst), "l"(src));
}

// ---- prepass: convert K,V fp32 -> bf16 hi/lo, once for the whole problem ----
__global__ __launch_bounds__(256)
void conv_kv(const float4* __restrict__ k4, const float4* __restrict__ v4)
{
    const int i = blockIdx.x * 256 + threadIdx.x;   // one float4 (4 elems) each
    float4 a = k4[i];
    uint2 hi, lo;
    split2(a.x, a.y, hi.x, lo.x);
    split2(a.z, a.w, hi.y, lo.y);
    ((uint2*)g_khi)[i] = hi;
    ((uint2*)g_klo)[i] = lo;
    float4 b = v4[i];
    split2(b.x, b.y, hi.x, lo.x);
    split2(b.z, b.w, hi.y, lo.y);
    ((uint2*)g_vhi)[i] = hi;
    ((uint2*)g_vlo)[i] = lo;
}

__global__ __launch_bounds__(NTH, 2)
void attn_mma(const float* __restrict__ q, const int* __restrict__ mask,
              const float* __restrict__ bias, float* __restrict__ out)
{
    extern __shared__ char smem[];
    __shared__ int s_len;
    __shared__ float s_li[64];
    const int tid  = threadIdx.x;
    const int lane = tid & 31;
    const int w    = tid >> 5;
    const int w_m  = w & 3;        // row group: rows 16*w_m .. +15
    const int w_n  = w >> 2;       // key half: keys 32*w_n .. +31 of each tile
    const int nh   = 32 * w_n;
    const int rowg = 16 * w_m;
    const int m0   = blockIdx.x * BM;
    const int h    = blockIdx.y;
    const int b    = blockIdx.z;
    const int bh   = b * NH + h;
    const uint32_t sb = smem_u32(smem);

    // per-thread cp.async slice: this half (128 threads) loads its own 32 rows;
    // 4 threads per row, each thread two 16B chunks per array.
    const int g    = tid & 127;                // id within the 128-thread half
    const int kr   = nh + (g >> 2);            // tile row (nh..nh+31)
    const int cc   = (g & 3) * 16;             // elem col base (2 chunks: cc, cc+8)
    const uint32_t kvoff0 = sw((uint32_t)kr * 128 + (uint32_t)cc * 2);
    const uint32_t kvoff1 = sw((uint32_t)kr * 128 + (uint32_t)cc * 2 + 16);
    const size_t   gsrc0  = ((size_t)bh * SEQ + kr) * DDIM + cc;

    // ---- issue tile-0 K/V cp.async immediately (overlaps Q conversion) ----
    {
        const uint32_t d = sb + SBUF;
        cpasync16(d + kvoff0,          g_khi + gsrc0);
        cpasync16(d + kvoff1,          g_khi + gsrc0 + 8);
        cpasync16(d + 8192  + kvoff0,  g_klo + gsrc0);
        cpasync16(d + 8192  + kvoff1,  g_klo + gsrc0 + 8);
        cpasync16(d + 16384 + kvoff0,  g_vhi + gsrc0);
        cpasync16(d + 16384 + kvoff1,  g_vhi + gsrc0 + 8);
        cpasync16(d + 24576 + kvoff0,  g_vlo + gsrc0);
        cpasync16(d + 24576 + kvoff1,  g_vlo + gsrc0 + 8);
        asm volatile("cp.async.commit_group;" ::: "memory");
    }

    if (tid == 0) s_len = 0;
    __syncthreads();
    {   // valid length (mask int32 0/1, monotone prefix)
        const int* mb = mask + (size_t)b * SEQ;
        int part = 0;
        for (int i = tid; i < SEQ; i += NTH) part += (mb[i] != 0);
        #pragma unroll
        for (int o = 16; o > 0; o >>= 1) part += __shfl_xor_sync(0xffffffffu, part, o);
        if (lane == 0) atomicAdd(&s_len, part);
    }

    // ---- Q tile fp32 -> bf16 hi/lo, swizzled [row][d] 128B rows ----
    {
        const int row  = tid >> 2;                 // 0..63
        const int colf = (tid & 3) * 16;           // float col base
        const float* qrow = q + (((size_t)bh) * SEQ + m0 + row) * DDIM + colf;
        #pragma unroll
        for (int c = 0; c < 2; c++) {              // 2 chunks of 8 floats
            float4 t0 = *(const float4*)(qrow + 8 * c);
            float4 t1 = *(const float4*)(qrow + 8 * c + 4);
            uint4 hv, lv;
            split2(t0.x, t0.y, hv.x, lv.x);
            split2(t0.z, t0.w, hv.y, lv.y);
            split2(t1.x, t1.y, hv.z, lv.z);
            split2(t1.z, t1.w, hv.w, lv.w);
            uint32_t off = sw(row * 128 + colf * 2 + 16 * c);
            *(uint4*)(smem + SQH + off) = hv;
            *(uint4*)(smem + SQL + off) = lv;
        }
    }
    __syncthreads();
    const int len = s_len;
    const int n_tiles = (len + BN - 1) / BN;

    // ldmatrix per-lane addressing pattern
    const int r8  = (lane & 7) + ((lane >> 3) & 1) * 8;
    const int c16 = ((lane >> 4) & 1) * 16;

    float o[8][4];
    #pragma unroll
    for (int i = 0; i < 8; i++)
        #pragma unroll
        for (int j = 0; j < 4; j++) o[i][j] = 0.0f;
    float li1 = 0.0f, li2 = 0.0f;

    const float* bp1 = bias + ((size_t)h * SEQ + (m0 + rowg + (lane >> 2))) * SEQ;
    const float* bp2 = bp1 + 8 * SEQ;

    for (int t = 0; t < n_tiles; t++) {
        const int n0 = t * BN;
        const uint32_t kvb = sb + SBUF + (uint32_t)(t & 1) * KVSTRIDE;

        // ---- bias prefetch (pre-scaled by log2(e); overlaps the wait) ----
        float2 bb1[4], bb2[4];
        #pragma unroll
        for (int nb = 0; nb < 4; nb++) {
            int c = n0 + nh + 8 * nb + (lane & 3) * 2;
            bb1[nb] = *(const float2*)(bp1 + c);
            bb2[nb] = *(const float2*)(bp2 + c);
            bb1[nb].x *= LOG2E; bb1[nb].y *= LOG2E;
            bb2[nb].x *= LOG2E; bb2[nb].y *= LOG2E;
        }

        // ---- tile t's cp.async group (issued last iteration) must be done ----
        asm volatile("cp.async.wait_group 0;" ::: "memory");
        asm volatile("bar.sync %0, 128;" :: "r"(1 + w_n) : "memory");

        // ---- issue next tile's K/V into the other buffer (WAR-safe: all
        //      reads of that buffer happened before the barrier above) ----
        if (t + 1 < n_tiles) {
            const uint32_t d = sb + SBUF + (uint32_t)((t + 1) & 1) * KVSTRIDE;
            const size_t src = gsrc0 + (size_t)(t + 1) * BN * DDIM;
            cpasync16(d + kvoff0,          g_khi + src);
            cpasync16(d + kvoff1,          g_khi + src + 8);
            cpasync16(d + 8192  + kvoff0,  g_klo + src);
            cpasync16(d + 8192  + kvoff1,  g_klo + src + 8);
            cpasync16(d + 16384 + kvoff0,  g_vhi + src);
            cpasync16(d + 16384 + kvoff1,  g_vhi + src + 8);
            cpasync16(d + 24576 + kvoff0,  g_vlo + src);
            cpasync16(d + 24576 + kvoff1,  g_vlo + src + 8);
        }
        asm volatile("cp.async.commit_group;" ::: "memory");

        // ---- GEMM1: S = QK^T over this warp's 32-key half, 3-way split ----
        float s[4][4];
        #pragma unroll
        for (int i = 0; i < 4; i++)
            #pragma unroll
            for (int j = 0; j < 4; j++) s[i][j] = 0.0f;
        #pragma unroll
        for (int kbk = 0; kbk < 4; kbk++) {
            uint32_t qoff = sw((rowg + r8) * 128 + 32 * kbk + c16);
            uint32_t a0, a1, a2, a3, e0, e1, e2, e3;
            ldsm4(a0, a1, a2, a3, sb + SQH + qoff);
            ldsm4(e0, e1, e2, e3, sb + SQL + qoff);
            #pragma unroll
            for (int nbp = 0; nbp < 2; nbp++) {
                uint32_t boff = sw((nh + 16 * nbp + r8) * 128 + 32 * kbk + c16);
                uint32_t bh0, bh1, bh2, bh3, bl0, bl1, bl2, bl3;
                ldsm4(bh0, bh1, bh2, bh3, kvb + boff);
                ldsm4(bl0, bl1, bl2, bl3, kvb + 8192 + boff);
                mma16816(s[2 * nbp],     a0, a1, a2, a3, bh0, bh2);
                mma16816(s[2 * nbp + 1], a0, a1, a2, a3, bh1, bh3);
                mma16816(s[2 * nbp],     e0, e1, e2, e3, bh0, bh2);
                mma16816(s[2 * nbp + 1], e0, e1, e2, e3, bh1, bh3);
                mma16816(s[2 * nbp],     a0, a1, a2, a3, bl0, bl2);
                mma16816(s[2 * nbp + 1], a0, a1, a2, a3, bl1, bl3);
            }
        }

        // ---- softmax: p = exp2(s*log2e + bias*log2e), no max-sub ----
        uint32_t pah[2][4], pal[2][4];
        #pragma unroll
        for (int nb = 0; nb < 4; nb++) {
            int n = n0 + nh + 8 * nb + (lane & 3) * 2;
            float p0 = (n     < len) ? exp2f(fmaf(s[nb][0], LOG2E, bb1[nb].x)) : 0.0f;
            float p1 = (n + 1 < len) ? exp2f(fmaf(s[nb][1], LOG2E, bb1[nb].y)) : 0.0f;
            float p2 = (n     < len) ? exp2f(fmaf(s[nb][2], LOG2E, bb2[nb].x)) : 0.0f;
            float p3 = (n + 1 < len) ? exp2f(fmaf(s[nb][3], LOG2E, bb2[nb].y)) : 0.0f;
            li1 += p0 + p1;
            li2 += p2 + p3;
            split2(p0, p1, pah[nb >> 1][(nb & 1) * 2],     pal[nb >> 1][(nb & 1) * 2]);
            split2(p2, p3, pah[nb >> 1][(nb & 1) * 2 + 1], pal[nb >> 1][(nb & 1) * 2 + 1]);
        }

        // ---- GEMM2: O(partial) += P V over this warp's 32 keys ----
        const uint32_t vh_ = kvb + 16384;
        const uint32_t vl_ = kvb + 24576;
        #pragma unroll
        for (int kk = 0; kk < 2; kk++) {
            #pragma unroll
            for (int nbp = 0; nbp < 4; nbp++) {
                uint32_t voff = sw((nh + 16 * kk + r8) * 128 + 32 * nbp + c16);
                uint32_t vh0, vh1, vh2, vh3, vl0, vl1, vl2, vl3;
                ldsm4t(vh0, vh1, vh2, vh3, vh_ + voff);
                ldsm4t(vl0, vl1, vl2, vl3, vl_ + voff);
                mma16816(o[2 * nbp],     pah[kk][0], pah[kk][1], pah[kk][2], pah[kk][3], vh0, vh1);
                mma16816(o[2 * nbp + 1], pah[kk][0], pah[kk][1], pah[kk][2], pah[kk][3], vh2, vh3);
                mma16816(o[2 * nbp],     pal[kk][0], pal[kk][1], pal[kk][2], pal[kk][3], vh0, vh1);
                mma16816(o[2 * nbp + 1], pal[kk][0], pal[kk][1], pal[kk][2], pal[kk][3], vh2, vh3);
                mma16816(o[2 * nbp],     pah[kk][0], pah[kk][1], pah[kk][2], pah[kk][3], vl0, vl1);
                mma16816(o[2 * nbp + 1], pah[kk][0], pah[kk][1], pah[kk][2], pah[kk][3], vl2, vl3);
            }
        }
    }

    // ---- reduce li across the quad (lanes l^1, l^2 hold the same rows) ----
    li1 += __shfl_xor_sync(0xffffffffu, li1, 1);
    li1 += __shfl_xor_sync(0xffffffffu, li1, 2);
    li2 += __shfl_xor_sync(0xffffffffu, li2, 1);
    li2 += __shfl_xor_sync(0xffffffffu, li2, 2);

    // ---- combine the two key-halves: O(partial) and li through smem ----
    __syncthreads();   // all GEMM2 smem reads done; safe to alias KV buffer 0
    float* oshare = (float*)(smem + SBUF);   // [64][64] fp32 = 16KB
    const int r1 = rowg + (lane >> 2);
    if (w_n == 1) {
        #pragma unroll
        for (int nb = 0; nb < 8; nb++) {
            int c = 8 * nb + (lane & 3) * 2;
            *(float2*)(oshare + r1 * 64 + c)       = make_float2(o[nb][0], o[nb][1]);
            *(float2*)(oshare + (r1 + 8) * 64 + c) = make_float2(o[nb][2], o[nb][3]);
        }
        if ((lane & 3) == 0) {
            s_li[r1]     = li1;
            s_li[r1 + 8] = li2;
        }
    }
    __syncthreads();

    if (w_n == 0) {
        const float lt1 = li1 + s_li[r1];
        const float lt2 = li2 + s_li[r1 + 8];
        const float inv1 = ((m0 + r1)     < len) ? (1.0f / lt1) : 0.0f;
        const float inv2 = ((m0 + r1 + 8) < len) ? (1.0f / lt2) : 0.0f;
        float* o1 = out + ((size_t)b * SEQ + m0 + r1) * (NH * DDIM) + (size_t)h * DDIM;
        float* o2 = o1 + 8 * (NH * DDIM);
        #pragma unroll
        for (int nb = 0; nb < 8; nb++) {
            int c = 8 * nb + (lane & 3) * 2;
            float2 q1 = *(const float2*)(oshare + r1 * 64 + c);
            float2 q2 = *(const float2*)(oshare + (r1 + 8) * 64 + c);
            float2 w1 = {(o[nb][0] + q1.x) * inv1, (o[nb][1] + q1.y) * inv1};
            float2 w2 = {(o[nb][2] + q2.x) * inv2, (o[nb][3] + q2.y) * inv2};
            *(float2*)(o1 + c) = w1;
            *(float2*)(o2 + c) = w2;
        }
    }
}

extern "C" void kernel_launch(void* const* d_in, const int* in_sizes, int n_in,
                              void* d_out, int out_size)
{
    const float* q    = (const float*)d_in[0];
    const float* k    = (const float*)d_in[1];
    const float* v    = (const float*)d_in[2];
    const int*   mask = (const int*)d_in[3];
    const float* bias = (const float*)d_in[4];
    float* out = (float*)d_out;

    conv_kv<<<KVELEMS / 4 / 256, 256>>>((const float4*)k, (const float4*)v);

    cudaFuncSetAttribute(attn_mma, cudaFuncAttributeMaxDynamicSharedMemorySize, SMTOT);
    dim3 grid(SEQ / BM, NH, NB);
    attn_mma<<<grid, NTH, SMTOT>>>(q, mask, bias, out);
}